// round 6
// baseline (speedup 1.0000x reference)
#include <cuda_runtime.h>

#define NB   8192
#define NOPT 16
#define DIM  768
#define F4_PER_ROW (DIM / 4)   // 192 float4 per row
#define F4_PER_SMP (NOPT * F4_PER_ROW)  // 3072
#define MARGIN 0.3f
#define GRID (NB / 2)

// Scratch: per-sample partials + completion counter (deterministic reduction).
__device__ float    g_loss[NB];
__device__ int      g_cnt[NB];
__device__ unsigned cf_counter = 0;   // returns to 0 at end of every launch

// pair index for (i<=j) in triangular enumeration; folds to a constant under unroll
__device__ __forceinline__ constexpr int pidx(int i, int j) {
    return i * NOPT - (i * (i - 1)) / 2 + (j - i);
}

template <int LO, int HI>
__device__ __forceinline__ void accum_pairs(float (&acc)[HI - LO], const float4 (&x)[NOPT]) {
#pragma unroll
    for (int i = 0; i < NOPT; ++i) {
#pragma unroll
        for (int j = i; j < NOPT; ++j) {
            const int p = pidx(i, j);
            if (p >= LO && p < HI) {
                float a = acc[p - LO];
                a = fmaf(x[i].x, x[j].x, a);
                a = fmaf(x[i].y, x[j].y, a);
                a = fmaf(x[i].z, x[j].z, a);
                a = fmaf(x[i].w, x[j].w, a);
                acc[p - LO] = a;
            }
        }
    }
}

template <int LO, int HI>
__device__ __forceinline__ void reduce_store(float (&acc)[HI - LO], float* G, int lane) {
#pragma unroll
    for (int i = 0; i < NOPT; ++i) {
#pragma unroll
        for (int j = i; j < NOPT; ++j) {
            const int p = pidx(i, j);
            if (p >= LO && p < HI) {
                float v = acc[p - LO];
                v += __shfl_xor_sync(0xFFFFFFFFu, v, 16);
                v += __shfl_xor_sync(0xFFFFFFFFu, v, 8);
                v += __shfl_xor_sync(0xFFFFFFFFu, v, 4);
                v += __shfl_xor_sync(0xFFFFFFFFu, v, 2);
                v += __shfl_xor_sync(0xFFFFFFFFu, v, 1);
                if (lane == 0) {
                    G[i * NOPT + j] = v;
                    G[j * NOPT + i] = v;
                }
            }
        }
    }
}

// Gram accumulation fed from the shared-memory tile (loaded once per sample).
template <int LO, int HI>
__device__ __forceinline__ void sample_work(const float4* __restrict__ tile,
                                            float* __restrict__ G, int lane) {
    float acc[HI - LO] = {};
    float4 x[NOPT];
    for (int k = 0; k < 6; ++k) {
        const float4* p0 = tile + lane + 32 * k;
#pragma unroll
        for (int n = 0; n < NOPT; ++n) x[n] = p0[n * F4_PER_ROW];
        accum_pairs<LO, HI>(acc, x);
    }
    reduce_store<LO, HI>(acc, G, lane);
}

// 128 threads = 2 samples x 2 warps. Tile staged in smem once (no duplicate
// GMEM reads); last CTA performs the grid reduction (no second launch).
__global__ void __launch_bounds__(128)
cf_fused(const float* __restrict__ emb, const long long* __restrict__ labels,
         float* __restrict__ out) {
    extern __shared__ float4 tile[];   // 2 * 3072 float4 = 96 KB

    __shared__ float G[2][NOPT * NOPT];
    __shared__ float invn[2][NOPT];
    __shared__ int   lab[2][NOPT];
    __shared__ float ssum[4];
    __shared__ int   scnt[4];
    __shared__ int   s_last;

    const int tid  = threadIdx.x;
    const int half = tid >> 6;            // sample within CTA
    const int ht   = tid & 63;            // thread within sample group
    const int wis  = (tid >> 5) & 1;      // warp-in-sample 0..1
    const int lane = tid & 31;
    const int b    = blockIdx.x * 2 + half;

    if (ht < NOPT) lab[half][ht] = (int)labels[(size_t)b * NOPT + ht];

    // Cooperative tile load: 3072 float4 per sample, 64 threads -> 48 each.
    {
        const float4* src = reinterpret_cast<const float4*>(emb + (size_t)b * NOPT * DIM);
        float4* dst = tile + half * F4_PER_SMP;
#pragma unroll
        for (int r = 0; r < 48; ++r) dst[ht + 64 * r] = src[ht + 64 * r];
    }
    __syncthreads();

    {
        const float4* t = tile + half * F4_PER_SMP;
        if (wis == 0) sample_work<0, 68>(t, G[half], lane);
        else          sample_work<68, 136>(t, G[half], lane);
    }
    __syncthreads();

    if (ht < NOPT) invn[half][ht] = rsqrtf(fmaxf(G[half][ht * NOPT + ht], 1e-24f));
    __syncthreads();

    if (ht < NOPT) {
        const int  n     = ht;
        const bool isPos = (lab[half][n] == 1);
        const bool isNeg = (lab[half][n] == 0);
        const unsigned posm = __ballot_sync(0x0000FFFFu, isPos) & 0xFFFFu;
        const unsigned negm = __ballot_sync(0x0000FFFFu, isNeg) & 0xFFFFu;
        const bool valid = (posm != 0u) && (negm != 0u);

        const float in_ = invn[half][n];
        float mx = -1e9f;   // NEG_INF sentinel, matches reference
#pragma unroll
        for (int m = 0; m < NOPT; ++m) {
            if (lab[half][m] == 0)
                mx = fmaxf(mx, G[half][n * NOPT + m] * in_ * invn[half][m]);
        }
        const float trip = fmaxf(mx + MARGIN, 0.0f);
        float contrib = (isPos && valid) ? trip : 0.0f;

        contrib += __shfl_xor_sync(0x0000FFFFu, contrib, 8);
        contrib += __shfl_xor_sync(0x0000FFFFu, contrib, 4);
        contrib += __shfl_xor_sync(0x0000FFFFu, contrib, 2);
        contrib += __shfl_xor_sync(0x0000FFFFu, contrib, 1);

        if (n == 0) {
            g_loss[b] = contrib;
            g_cnt[b]  = valid ? __popc(posm) : 0;
        }
    }

    // Writers (tid 0 / tid 64) publish, then one arrival per CTA.
    if (ht == 0) __threadfence();
    __syncthreads();
    if (tid == 0) {
        const unsigned t = atomicAdd(&cf_counter, 1u);
        s_last = (t == GRID - 1);
    }
    __syncthreads();

    if (s_last) {
        // Last CTA: fixed-order grid reduction (deterministic). L2 reads via
        // __ldcg avoid any stale-L1 concern for cross-SM-written data.
        float s = 0.0f;
        int   c = 0;
#pragma unroll 8
        for (int i = tid; i < NB; i += 128) {
            s += __ldcg(&g_loss[i]);
            c += __ldcg(&g_cnt[i]);
        }
#pragma unroll
        for (int off = 16; off > 0; off >>= 1) {
            s += __shfl_xor_sync(0xFFFFFFFFu, s, off);
            c += __shfl_xor_sync(0xFFFFFFFFu, c, off);
        }
        if (lane == 0) { ssum[tid >> 5] = s; scnt[tid >> 5] = c; }
        __syncthreads();
        if (tid == 0) {
            const float st = (ssum[0] + ssum[1]) + (ssum[2] + ssum[3]);
            const int   ct = (scnt[0] + scnt[1]) + (scnt[2] + scnt[3]);
            out[0] = st / (float)(ct > 0 ? ct : 1);
            cf_counter = 0;   // reset for next graph replay
        }
    }
}

extern "C" void kernel_launch(void* const* d_in, const int* in_sizes, int n_in,
                              void* d_out, int out_size) {
    const float*     emb    = (const float*)d_in[0];
    const long long* labels = (const long long*)d_in[1];
    float*           out    = (float*)d_out;

    static bool attr_set = false;
    if (!attr_set) {
        cudaFuncSetAttribute(cf_fused, cudaFuncAttributeMaxDynamicSharedMemorySize,
                             2 * F4_PER_SMP * (int)sizeof(float4));
        attr_set = true;
    }

    cf_fused<<<GRID, 128, 2 * F4_PER_SMP * sizeof(float4)>>>(emb, labels, out);
}